// round 2
// baseline (speedup 1.0000x reference)
#include <cuda_runtime.h>
#include <cstdint>
#include <math_constants.h>

// ---------------------------------------------------------------------------
// NF4 block quant-dequant (blocksize 512), exact classification.
//
// Per 512-block: absmax -> xn = x/absmax -> searchsorted over 15 midpoints
// -> out = NF4[idx] * absmax.
//
// Exact-LUT scheme: 256 cells over xn in [-1,1] (width 1/128 = 0.0078, less
// than the minimum boundary spacing 0.085, so each cell contains AT MOST ONE
// decision boundary). Cell j stores {mid, code_lo, code_hi}:
//   idx(v) = idx_at_left_edge + (v > mid)
// which reproduces searchsorted exactly. Cells without a boundary store
// mid=+1e30 and lo==hi. One LDS.128 + compare + select per element.
// ---------------------------------------------------------------------------

#define NCELLS   256
#define HALFCELL 128.0f
#define QBLOCK   512

__device__ float4 g_lut[NCELLS];   // {mid, code_lo, code_hi, unused}

__constant__ float c_nf4[16] = {
    -1.0f, -0.6961928009986877f, -0.5250730514526367f, -0.39491748809814453f,
    -0.28444138169288635f, -0.18477343022823334f, -0.09105003625154495f, 0.0f,
    0.07958029955625534f, 0.16093020141124725f, 0.24611230194568634f,
    0.33791524171829224f, 0.4407098591327667f, 0.5626170039176941f,
    0.7229568362236023f, 1.0f
};

// Build the 256-entry {mid, lo, hi} LUT. fp32 throughout, matching reference.
__global__ void nf4_build_lut_kernel() {
    int j = threadIdx.x;
    if (j >= NCELLS) return;

    float L = (float)j * (1.0f / HALFCELL) - 1.0f;        // cell left edge (exact)
    float R = (float)(j + 1) * (1.0f / HALFCELL) - 1.0f;  // cell right edge (exact)

    // mids in fp32, identical to reference MID
    float mid[15];
#pragma unroll
    for (int i = 0; i < 15; i++) mid[i] = (c_nf4[i] + c_nf4[i + 1]) * 0.5f;

    // idx at left edge: #{ mid_i < L }   (no mid coincides with a cell edge)
    int idxL = 0;
#pragma unroll
    for (int i = 0; i < 15; i++) idxL += (mid[i] < L) ? 1 : 0;

    // boundary inside (L, R)?
    float m = 1e30f;
    int hi_idx = idxL;
#pragma unroll
    for (int i = 0; i < 15; i++) {
        if (mid[i] > L && mid[i] < R) { m = mid[i]; hi_idx = i + 1; }
    }

    float4 e;
    e.x = m;                 // decision boundary (or +big => always 'lo')
    e.y = c_nf4[idxL];       // code for v <= mid
    e.z = c_nf4[hi_idx];     // code for v >  mid
    e.w = 0.0f;
    g_lut[j] = e;
}

__global__ void __launch_bounds__(256)
nf4_quant_dequant_kernel(const float* __restrict__ x,
                         float* __restrict__ out,
                         int n_qblocks) {
    __shared__ float4 lut[NCELLS];

    for (int i = threadIdx.x; i < NCELLS; i += blockDim.x)
        lut[i] = g_lut[i];
    __syncthreads();

    const int lane   = threadIdx.x & 31;
    const int warp   = (blockIdx.x * blockDim.x + threadIdx.x) >> 5;
    const int nwarps = (gridDim.x * blockDim.x) >> 5;

    for (int b = warp; b < n_qblocks; b += nwarps) {
        const float4* src = (const float4*)(x + (size_t)b * QBLOCK);
        float4* dst       = (float4*)(out + (size_t)b * QBLOCK);

        float4 v0 = src[lane];
        float4 v1 = src[lane + 32];
        float4 v2 = src[lane + 64];
        float4 v3 = src[lane + 96];

        // per-thread absmax over 16 values
        float m;
        m = fabsf(v0.x);
        m = fmaxf(m, fabsf(v0.y)); m = fmaxf(m, fabsf(v0.z)); m = fmaxf(m, fabsf(v0.w));
        m = fmaxf(m, fabsf(v1.x)); m = fmaxf(m, fabsf(v1.y));
        m = fmaxf(m, fabsf(v1.z)); m = fmaxf(m, fabsf(v1.w));
        m = fmaxf(m, fabsf(v2.x)); m = fmaxf(m, fabsf(v2.y));
        m = fmaxf(m, fabsf(v2.z)); m = fmaxf(m, fabsf(v2.w));
        m = fmaxf(m, fabsf(v3.x)); m = fmaxf(m, fabsf(v3.y));
        m = fmaxf(m, fabsf(v3.z)); m = fmaxf(m, fabsf(v3.w));

        // warp-wide absmax (quant block == one warp's 512 elements)
#pragma unroll
        for (int off = 16; off > 0; off >>= 1)
            m = fmaxf(m, __shfl_xor_sync(0xffffffffu, m, off));

        const float scale    = (m == 0.0f) ? 1.0f : m;
        const float invscale = 1.0f / scale;   // one IEEE divide per block

        // xn = v*invscale (<=2ulp vs reference v/scale; boundary-flip odds ~0)
#define NF4_DEQ(val)                                                       \
        ({ float _xn = (val) * invscale;                                   \
           float _t  = fminf(fmaf(_xn, HALFCELL, HALFCELL),                \
                             (float)(NCELLS - 1));                         \
           float4 _e = lut[(int)_t];                                       \
           ((_xn > _e.x) ? _e.z : _e.y) * m; })

        float4 o;
        o.x = NF4_DEQ(v0.x); o.y = NF4_DEQ(v0.y);
        o.z = NF4_DEQ(v0.z); o.w = NF4_DEQ(v0.w);
        dst[lane] = o;
        o.x = NF4_DEQ(v1.x); o.y = NF4_DEQ(v1.y);
        o.z = NF4_DEQ(v1.z); o.w = NF4_DEQ(v1.w);
        dst[lane + 32] = o;
        o.x = NF4_DEQ(v2.x); o.y = NF4_DEQ(v2.y);
        o.z = NF4_DEQ(v2.z); o.w = NF4_DEQ(v2.w);
        dst[lane + 64] = o;
        o.x = NF4_DEQ(v3.x); o.y = NF4_DEQ(v3.y);
        o.z = NF4_DEQ(v3.z); o.w = NF4_DEQ(v3.w);
        dst[lane + 96] = o;
#undef NF4_DEQ
    }
}

extern "C" void kernel_launch(void* const* d_in, const int* in_sizes, int n_in,
                              void* d_out, int out_size) {
    const float* x = (const float*)d_in[0];
    float* out = (float*)d_out;
    const int n = in_sizes[0];
    const int n_qblocks = n / QBLOCK;   // 65536 for 4096x8192

    nf4_build_lut_kernel<<<1, NCELLS>>>();

    const int threads = 256;
    const int ctas = 1184;   // ~148 SMs * 8 CTAs, warps grid-stride over blocks
    nf4_quant_dequant_kernel<<<ctas, threads>>>(x, out, n_qblocks);
}

// round 3
// speedup vs baseline: 1.4355x; 1.4355x over previous
#include <cuda_runtime.h>
#include <cstdint>

// ---------------------------------------------------------------------------
// NF4 block quant-dequant (blocksize 512), exact classification, zero shared
// memory in the hot path.
//
// Warp-register LUT: 32 cells over xn in [-1,1] (width 1/16 = 0.0625, below
// the minimum NF4 boundary spacing ~0.082, so each cell holds AT MOST ONE
// decision boundary). Lane c of every warp holds:
//   mid_lane  = the boundary inside cell c (or +1e30 if none)
//   left_lane = codebook value valid at cell c's LEFT edge
// Element lookup: cell c -> shfl(mid) -> c += (xn > mid) -> shfl(left).
// Since the code to the right of a boundary equals the code at the next
// cell's left edge, this reproduces searchsorted exactly.
// ---------------------------------------------------------------------------

#define QBLOCK 512

__constant__ float c_nf4[16] = {
    -1.0f, -0.6961928009986877f, -0.5250730514526367f, -0.39491748809814453f,
    -0.28444138169288635f, -0.18477343022823334f, -0.09105003625154495f, 0.0f,
    0.07958029955625534f, 0.16093020141124725f, 0.24611230194568634f,
    0.33791524171829224f, 0.4407098591327667f, 0.5626170039176941f,
    0.7229568362236023f, 1.0f
};

__global__ void __launch_bounds__(256)
nf4_quant_dequant_kernel(const float* __restrict__ x,
                         float* __restrict__ out,
                         int n_qblocks) {
    const int lane = threadIdx.x & 31;

    // --- Build per-lane cell entry (once; pure register state) -----------
    float mid_lane = 1e30f;   // decision boundary inside this lane's cell
    float left_lane;          // codebook value at this cell's left edge
    {
        const float L = (float)lane * 0.0625f - 1.0f;
        const float R = L + 0.0625f;
        int idxL = 0;
#pragma unroll
        for (int i = 0; i < 15; i++) {
            float md = (c_nf4[i] + c_nf4[i + 1]) * 0.5f;   // fp32, == ref MID
            idxL += (md < L) ? 1 : 0;
            if (md > L && md < R) mid_lane = md;
        }
        left_lane = c_nf4[idxL];
    }

    const int warp   = (blockIdx.x * blockDim.x + threadIdx.x) >> 5;
    const int nwarps = (gridDim.x * blockDim.x) >> 5;

    for (int b = warp; b < n_qblocks; b += nwarps) {
        const float4* src = (const float4*)(x + (size_t)b * QBLOCK);
        float4* dst       = (float4*)(out + (size_t)b * QBLOCK);

        float4 v0 = src[lane];
        float4 v1 = src[lane + 32];
        float4 v2 = src[lane + 64];
        float4 v3 = src[lane + 96];

        // per-thread absmax over 16 values
        float m;
        m = fabsf(v0.x);
        m = fmaxf(m, fabsf(v0.y)); m = fmaxf(m, fabsf(v0.z)); m = fmaxf(m, fabsf(v0.w));
        m = fmaxf(m, fabsf(v1.x)); m = fmaxf(m, fabsf(v1.y));
        m = fmaxf(m, fabsf(v1.z)); m = fmaxf(m, fabsf(v1.w));
        m = fmaxf(m, fabsf(v2.x)); m = fmaxf(m, fabsf(v2.y));
        m = fmaxf(m, fabsf(v2.z)); m = fmaxf(m, fabsf(v2.w));
        m = fmaxf(m, fabsf(v3.x)); m = fmaxf(m, fabsf(v3.y));
        m = fmaxf(m, fabsf(v3.z)); m = fmaxf(m, fabsf(v3.w));

        // warp-wide absmax (quant block == one warp's 512 elements)
#pragma unroll
        for (int off = 16; off > 0; off >>= 1)
            m = fmaxf(m, __shfl_xor_sync(0xffffffffu, m, off));

        const float scale    = (m == 0.0f) ? 1.0f : m;
        const float invscale = 1.0f / scale;   // one IEEE divide per block

#define NF4_DEQ(val)                                                        \
        ({ float _xn = (val) * invscale;                                    \
           int _c = (int)fminf(fmaf(_xn, 16.0f, 16.0f), 31.0f);             \
           float _mid = __shfl_sync(0xffffffffu, mid_lane, _c);             \
           _c += (_xn > _mid) ? 1 : 0;                                      \
           __shfl_sync(0xffffffffu, left_lane, _c) * m; })

        float4 o;
        o.x = NF4_DEQ(v0.x); o.y = NF4_DEQ(v0.y);
        o.z = NF4_DEQ(v0.z); o.w = NF4_DEQ(v0.w);
        dst[lane] = o;
        o.x = NF4_DEQ(v1.x); o.y = NF4_DEQ(v1.y);
        o.z = NF4_DEQ(v1.z); o.w = NF4_DEQ(v1.w);
        dst[lane + 32] = o;
        o.x = NF4_DEQ(v2.x); o.y = NF4_DEQ(v2.y);
        o.z = NF4_DEQ(v2.z); o.w = NF4_DEQ(v2.w);
        dst[lane + 64] = o;
        o.x = NF4_DEQ(v3.x); o.y = NF4_DEQ(v3.y);
        o.z = NF4_DEQ(v3.z); o.w = NF4_DEQ(v3.w);
        dst[lane + 96] = o;
#undef NF4_DEQ
    }
}

extern "C" void kernel_launch(void* const* d_in, const int* in_sizes, int n_in,
                              void* d_out, int out_size) {
    const float* x = (const float*)d_in[0];
    float* out = (float*)d_out;
    const int n = in_sizes[0];
    const int n_qblocks = n / QBLOCK;   // 65536 for 4096x8192

    const int threads = 256;
    const int ctas = 2368;   // 148 SMs * 16 CTAs queued; warps grid-stride
    nf4_quant_dequant_kernel<<<ctas, threads>>>(x, out, n_qblocks);
}

// round 4
// speedup vs baseline: 1.4433x; 1.0055x over previous
#include <cuda_runtime.h>
#include <cstdint>

// ---------------------------------------------------------------------------
// NF4 block quant-dequant (blocksize 512), exact classification.
//
// Warp-register LUT (32 cells over [-1,1]; min NF4 boundary spacing ~0.082 >
// cell width 0.0625, so <=1 decision boundary per cell). Lane c holds:
//   mid_lane  = boundary inside cell c (+1e30 if none)
//   left_lane = codebook value at cell c's left edge
// Element: cell c -> shfl(mid*scale) -> c += (v > mid_s) -> shfl(left) * absmax.
//
// R4: 2 quant blocks per warp iteration (8 front-batched LDG.128, MLP=8;
// two independent absmax shfl chains interleave), perfectly uniform schedule
// (16384 warps x exactly 2 pair-iters), v-space compare, streaming ld/st.
// ---------------------------------------------------------------------------

#define QBLOCK 512

__constant__ float c_nf4[16] = {
    -1.0f, -0.6961928009986877f, -0.5250730514526367f, -0.39491748809814453f,
    -0.28444138169288635f, -0.18477343022823334f, -0.09105003625154495f, 0.0f,
    0.07958029955625534f, 0.16093020141124725f, 0.24611230194568634f,
    0.33791524171829224f, 0.4407098591327667f, 0.5626170039176941f,
    0.7229568362236023f, 1.0f
};

__global__ void __launch_bounds__(256)
nf4_quant_dequant_kernel(const float* __restrict__ x,
                         float* __restrict__ out,
                         int n_pairs) {   // n_qblocks/2
    const int lane = threadIdx.x & 31;

    // --- per-lane cell entry (registers only) ----------------------------
    float mid_lane = 1e30f;
    float left_lane;
    {
        const float L = (float)lane * 0.0625f - 1.0f;
        const float R = L + 0.0625f;
        int idxL = 0;
#pragma unroll
        for (int i = 0; i < 15; i++) {
            float md = (c_nf4[i] + c_nf4[i + 1]) * 0.5f;   // fp32 == ref MID
            idxL += (md < L) ? 1 : 0;
            if (md > L && md < R) mid_lane = md;
        }
        left_lane = c_nf4[idxL];
    }

    const int warp   = (blockIdx.x * blockDim.x + threadIdx.x) >> 5;
    const int nwarps = (gridDim.x * blockDim.x) >> 5;

    for (int p = warp; p < n_pairs; p += nwarps) {
        const float4* s0 = (const float4*)(x + (size_t)p * (2 * QBLOCK));
        const float4* s1 = s0 + (QBLOCK / 4);
        float4* d0       = (float4*)(out + (size_t)p * (2 * QBLOCK));
        float4* d1       = d0 + (QBLOCK / 4);

        // 8 front-batched 128-bit streaming loads (MLP = 8)
        float4 a0 = __ldcs(s0 + lane);
        float4 a1 = __ldcs(s0 + lane + 32);
        float4 a2 = __ldcs(s0 + lane + 64);
        float4 a3 = __ldcs(s0 + lane + 96);
        float4 b0 = __ldcs(s1 + lane);
        float4 b1 = __ldcs(s1 + lane + 32);
        float4 b2 = __ldcs(s1 + lane + 64);
        float4 b3 = __ldcs(s1 + lane + 96);

        // two independent absmax chains
        float m0, m1;
        m0 = fabsf(a0.x);
        m0 = fmaxf(m0, fabsf(a0.y)); m0 = fmaxf(m0, fabsf(a0.z)); m0 = fmaxf(m0, fabsf(a0.w));
        m0 = fmaxf(m0, fabsf(a1.x)); m0 = fmaxf(m0, fabsf(a1.y));
        m0 = fmaxf(m0, fabsf(a1.z)); m0 = fmaxf(m0, fabsf(a1.w));
        m0 = fmaxf(m0, fabsf(a2.x)); m0 = fmaxf(m0, fabsf(a2.y));
        m0 = fmaxf(m0, fabsf(a2.z)); m0 = fmaxf(m0, fabsf(a2.w));
        m0 = fmaxf(m0, fabsf(a3.x)); m0 = fmaxf(m0, fabsf(a3.y));
        m0 = fmaxf(m0, fabsf(a3.z)); m0 = fmaxf(m0, fabsf(a3.w));
        m1 = fabsf(b0.x);
        m1 = fmaxf(m1, fabsf(b0.y)); m1 = fmaxf(m1, fabsf(b0.z)); m1 = fmaxf(m1, fabsf(b0.w));
        m1 = fmaxf(m1, fabsf(b1.x)); m1 = fmaxf(m1, fabsf(b1.y));
        m1 = fmaxf(m1, fabsf(b1.z)); m1 = fmaxf(m1, fabsf(b1.w));
        m1 = fmaxf(m1, fabsf(b2.x)); m1 = fmaxf(m1, fabsf(b2.y));
        m1 = fmaxf(m1, fabsf(b2.z)); m1 = fmaxf(m1, fabsf(b2.w));
        m1 = fmaxf(m1, fabsf(b3.x)); m1 = fmaxf(m1, fabsf(b3.y));
        m1 = fmaxf(m1, fabsf(b3.z)); m1 = fmaxf(m1, fabsf(b3.w));

        // warp reductions (independent chains interleave)
#pragma unroll
        for (int off = 16; off > 0; off >>= 1) {
            m0 = fmaxf(m0, __shfl_xor_sync(0xffffffffu, m0, off));
            m1 = fmaxf(m1, __shfl_xor_sync(0xffffffffu, m1, off));
        }

        const float sc0 = (m0 == 0.0f) ? 1.0f : m0;
        const float sc1 = (m1 == 0.0f) ? 1.0f : m1;
        const float r0  = 16.0f / sc0;          // one divide per block
        const float r1  = 16.0f / sc1;
        const float ms0 = mid_lane * sc0;       // lane-local: this cell's
        const float ms1 = mid_lane * sc1;       //   boundary in v-space

#define NF4_DEQ(val, rr, msv, mm)                                           \
        ({ float _t = fminf(fmaf((val), (rr), 16.0f), 31.0f);               \
           int _c = (int)_t;                                                \
           float _mid = __shfl_sync(0xffffffffu, (msv), _c);                \
           _c += ((val) > _mid) ? 1 : 0;                                    \
           __shfl_sync(0xffffffffu, left_lane, _c) * (mm); })

        float4 o;
        o.x = NF4_DEQ(a0.x, r0, ms0, m0); o.y = NF4_DEQ(a0.y, r0, ms0, m0);
        o.z = NF4_DEQ(a0.z, r0, ms0, m0); o.w = NF4_DEQ(a0.w, r0, ms0, m0);
        __stcs(d0 + lane, o);
        o.x = NF4_DEQ(a1.x, r0, ms0, m0); o.y = NF4_DEQ(a1.y, r0, ms0, m0);
        o.z = NF4_DEQ(a1.z, r0, ms0, m0); o.w = NF4_DEQ(a1.w, r0, ms0, m0);
        __stcs(d0 + lane + 32, o);
        o.x = NF4_DEQ(a2.x, r0, ms0, m0); o.y = NF4_DEQ(a2.y, r0, ms0, m0);
        o.z = NF4_DEQ(a2.z, r0, ms0, m0); o.w = NF4_DEQ(a2.w, r0, ms0, m0);
        __stcs(d0 + lane + 64, o);
        o.x = NF4_DEQ(a3.x, r0, ms0, m0); o.y = NF4_DEQ(a3.y, r0, ms0, m0);
        o.z = NF4_DEQ(a3.z, r0, ms0, m0); o.w = NF4_DEQ(a3.w, r0, ms0, m0);
        __stcs(d0 + lane + 96, o);

        o.x = NF4_DEQ(b0.x, r1, ms1, m1); o.y = NF4_DEQ(b0.y, r1, ms1, m1);
        o.z = NF4_DEQ(b0.z, r1, ms1, m1); o.w = NF4_DEQ(b0.w, r1, ms1, m1);
        __stcs(d1 + lane, o);
        o.x = NF4_DEQ(b1.x, r1, ms1, m1); o.y = NF4_DEQ(b1.y, r1, ms1, m1);
        o.z = NF4_DEQ(b1.z, r1, ms1, m1); o.w = NF4_DEQ(b1.w, r1, ms1, m1);
        __stcs(d1 + lane + 32, o);
        o.x = NF4_DEQ(b2.x, r1, ms1, m1); o.y = NF4_DEQ(b2.y, r1, ms1, m1);
        o.z = NF4_DEQ(b2.z, r1, ms1, m1); o.w = NF4_DEQ(b2.w, r1, ms1, m1);
        __stcs(d1 + lane + 64, o);
        o.x = NF4_DEQ(b3.x, r1, ms1, m1); o.y = NF4_DEQ(b3.y, r1, ms1, m1);
        o.z = NF4_DEQ(b3.z, r1, ms1, m1); o.w = NF4_DEQ(b3.w, r1, ms1, m1);
        __stcs(d1 + lane + 96, o);
#undef NF4_DEQ
    }
}

extern "C" void kernel_launch(void* const* d_in, const int* in_sizes, int n_in,
                              void* d_out, int out_size) {
    const float* x = (const float*)d_in[0];
    float* out = (float*)d_out;
    const int n = in_sizes[0];
    const int n_pairs = n / (2 * QBLOCK);   // 32768 for 4096x8192

    // 2048 CTAs x 8 warps = 16384 warps; each does EXACTLY 2 pair-iterations
    // (32768 pairs) -> zero warp-level load imbalance.
    nf4_quant_dequant_kernel<<<2048, 256>>>(x, out, n_pairs);
}